// round 12
// baseline (speedup 1.0000x reference)
#include <cuda_runtime.h>
#include <cuda_bf16.h>
#include <math.h>
#include <stdint.h>

#define B_  2
#define T_  2048
#define D_  2048
#define H_  16
#define G_  4
#define HD_ 128

// ---------------- scratch (static device globals; no allocation) ----------------
__device__ float g_qg[(size_t)B_ * T_ * H_ * 2 * HD_];
__device__ float g_q [(size_t)B_ * H_ * T_ * HD_];
__device__ float g_k [(size_t)B_ * T_ * G_ * HD_];
__device__ float g_v [(size_t)B_ * T_ * G_ * HD_];
__device__ float g_attn[(size_t)B_ * T_ * H_ * HD_];
__device__ float g_xt [(size_t)B_ * T_ * D_];
__device__ float g_wqt[(size_t)D_ * 2 * H_ * HD_];
__device__ float g_wkt[(size_t)D_ * G_ * HD_];
__device__ float g_wvt[(size_t)D_ * G_ * HD_];
__device__ float g_wot[(size_t)H_ * HD_ * D_];

// ---------------- tf32 helpers ----------------
__device__ __forceinline__ unsigned f2tf32(float x) {
    unsigned r;
    asm("cvt.rna.tf32.f32 %0, %1;" : "=r"(r) : "f"(x));
    return r;
}

__device__ __forceinline__ void mma_tf32(float* c, unsigned a0, unsigned a1, unsigned a2,
                                         unsigned a3, unsigned b0, unsigned b1) {
    asm volatile(
        "mma.sync.aligned.m16n8k8.row.col.f32.tf32.tf32.f32 "
        "{%0,%1,%2,%3}, {%4,%5,%6,%7}, {%8,%9}, {%0,%1,%2,%3};\n"
        : "+f"(c[0]), "+f"(c[1]), "+f"(c[2]), "+f"(c[3])
        : "r"(a0), "r"(a1), "r"(a2), "r"(a3), "r"(b0), "r"(b1));
}

__global__ void cvt_tf32(const float* __restrict__ in, float* __restrict__ out, int n4) {
    int i = blockIdx.x * blockDim.x + threadIdx.x;
    if (i < n4) {
        float4 v = ((const float4*)in)[i];
        uint4 o;
        o.x = f2tf32(v.x); o.y = f2tf32(v.y); o.z = f2tf32(v.z); o.w = f2tf32(v.w);
        ((uint4*)out)[i] = o;
    }
}

#define APITCH 20
#define BPITCH 136

__device__ __forceinline__ void cp16(float* smem_dst, const float* gsrc) {
    unsigned sa = (unsigned)__cvta_generic_to_shared(smem_dst);
    asm volatile("cp.async.cg.shared.global [%0], [%1], 16;\n" :: "r"(sa), "l"(gsrc));
}

// ---------------- tf32 GEMM, 128x128 tile (proven; used for w_k / w_v) ----------------
__global__ __launch_bounds__(256, 2) void gemm_tf32(
        const float* __restrict__ A, const float* __restrict__ Bm,
        float* __restrict__ C, int M, int N, int K) {
    __shared__ float As[2][128 * APITCH];
    __shared__ float Bs[2][16 * BPITCH];

    int tid  = threadIdx.x;
    int lane = tid & 31;
    int warp = tid >> 5;
    int wm = (warp & 1) * 64;
    int wn = (warp >> 1) * 32;
    int bx = blockIdx.x, by = blockIdx.y;

    const float* Ab = A + (size_t)by * 128 * K;
    const float* Bb = Bm + (size_t)bx * 128;

    int a0row = tid >> 2,          a0kc = tid & 3;
    int a1row = (tid + 256) >> 2,  a1kc = tid & 3;
    int b0row = tid >> 5,          b0nc = tid & 31;
    int b1row = (tid + 256) >> 5,  b1nc = tid & 31;

    float acc[4][4][4];
#pragma unroll
    for (int i = 0; i < 4; i++)
#pragma unroll
        for (int j = 0; j < 4; j++)
#pragma unroll
            for (int c = 0; c < 4; c++) acc[i][j][c] = 0.f;

    int nk = K / 16;

    {
        cp16(&As[0][a0row * APITCH + a0kc * 4], Ab + (size_t)a0row * K + a0kc * 4);
        cp16(&As[0][a1row * APITCH + a1kc * 4], Ab + (size_t)a1row * K + a1kc * 4);
        cp16(&Bs[0][b0row * BPITCH + b0nc * 4], Bb + (size_t)b0row * N + b0nc * 4);
        cp16(&Bs[0][b1row * BPITCH + b1nc * 4], Bb + (size_t)b1row * N + b1nc * 4);
        asm volatile("cp.async.commit_group;\n");
    }

    int buf = 0;
    for (int kt = 0; kt < nk; kt++) {
        asm volatile("cp.async.wait_group 0;\n");
        __syncthreads();

        if (kt + 1 < nk) {
            int kb = (kt + 1) * 16;
            int nb = buf ^ 1;
            cp16(&As[nb][a0row * APITCH + a0kc * 4], Ab + (size_t)a0row * K + kb + a0kc * 4);
            cp16(&As[nb][a1row * APITCH + a1kc * 4], Ab + (size_t)a1row * K + kb + a1kc * 4);
            cp16(&Bs[nb][b0row * BPITCH + b0nc * 4], Bb + (size_t)(kb + b0row) * N + b0nc * 4);
            cp16(&Bs[nb][b1row * BPITCH + b1nc * 4], Bb + (size_t)(kb + b1row) * N + b1nc * 4);
        }
        asm volatile("cp.async.commit_group;\n");

        const float* Asb = As[buf];
        const float* Bsb = Bs[buf];
        int r  = lane >> 2;
        int kc = lane & 3;
#pragma unroll
        for (int ks = 0; ks < 2; ks++) {
            int k0 = ks * 8;
            unsigned af[4][4];
#pragma unroll
            for (int mf = 0; mf < 4; mf++) {
                int m = wm + mf * 16;
                af[mf][0] = __float_as_uint(Asb[(m + r)     * APITCH + k0 + kc]);
                af[mf][1] = __float_as_uint(Asb[(m + r + 8) * APITCH + k0 + kc]);
                af[mf][2] = __float_as_uint(Asb[(m + r)     * APITCH + k0 + kc + 4]);
                af[mf][3] = __float_as_uint(Asb[(m + r + 8) * APITCH + k0 + kc + 4]);
            }
            unsigned bf[4][2];
#pragma unroll
            for (int nf = 0; nf < 4; nf++) {
                int n = wn + nf * 8;
                bf[nf][0] = __float_as_uint(Bsb[(k0 + kc)     * BPITCH + n + r]);
                bf[nf][1] = __float_as_uint(Bsb[(k0 + kc + 4) * BPITCH + n + r]);
            }
#pragma unroll
            for (int mf = 0; mf < 4; mf++)
#pragma unroll
                for (int nf = 0; nf < 4; nf++)
                    mma_tf32(acc[mf][nf], af[mf][0], af[mf][1], af[mf][2], af[mf][3],
                             bf[nf][0], bf[nf][1]);
        }
        buf ^= 1;
    }

    int r  = lane >> 2;
    int cc = (lane & 3) * 2;
#pragma unroll
    for (int mf = 0; mf < 4; mf++) {
#pragma unroll
        for (int nf = 0; nf < 4; nf++) {
            size_t row0 = (size_t)(by * 128 + wm + mf * 16 + r);
            int col = bx * 128 + wn + nf * 8 + cc;
            *(float2*)&C[row0 * N + col]       = make_float2(acc[mf][nf][0], acc[mf][nf][1]);
            *(float2*)&C[(row0 + 8) * N + col] = make_float2(acc[mf][nf][2], acc[mf][nf][3]);
        }
    }
}

// ---------------- tf32 GEMM, 256x128 tile (w_q / w_o): better reuse ----------------
// 8 warps in 4(M)x2(N) layout, 64x64 per warp. Dynamic smem (58368 B), 1 CTA/SM.
#define G2_SMEM ((2 * 256 * APITCH + 2 * 16 * BPITCH) * 4)

__global__ __launch_bounds__(256, 1) void gemm_tf32_256(
        const float* __restrict__ A, const float* __restrict__ Bm,
        float* __restrict__ C, int M, int N, int K) {
    extern __shared__ float dsm[];
    float* As0 = dsm;                       // 256 x APITCH
    float* As1 = As0 + 256 * APITCH;
    float* Bs0 = As1 + 256 * APITCH;        // 16 x BPITCH
    float* Bs1 = Bs0 + 16 * BPITCH;
    float* AsA[2] = {As0, As1};
    float* BsA[2] = {Bs0, Bs1};

    int tid  = threadIdx.x;
    int lane = tid & 31;
    int warp = tid >> 5;
    int wm = (warp >> 1) * 64;   // 4 M groups
    int wn = (warp & 1) * 64;    // 2 N groups
    int bx = blockIdx.x, by = blockIdx.y;

    const float* Ab = A + (size_t)by * 256 * K;
    const float* Bb = Bm + (size_t)bx * 128;

    // A: 1024 chunks (row=c>>2, kc=c&3), 4 per thread. B: 512 chunks, 2 per thread.
    int arow[4], akc = tid & 3;
#pragma unroll
    for (int j = 0; j < 4; j++) arow[j] = (tid + 256 * j) >> 2;
    int b0row = tid >> 5,          b0nc = tid & 31;
    int b1row = (tid + 256) >> 5,  b1nc = tid & 31;

    float acc[4][8][4];
#pragma unroll
    for (int i = 0; i < 4; i++)
#pragma unroll
        for (int j = 0; j < 8; j++)
#pragma unroll
            for (int c = 0; c < 4; c++) acc[i][j][c] = 0.f;

    int nk = K / 16;

    {
#pragma unroll
        for (int j = 0; j < 4; j++)
            cp16(&As0[arow[j] * APITCH + akc * 4], Ab + (size_t)arow[j] * K + akc * 4);
        cp16(&Bs0[b0row * BPITCH + b0nc * 4], Bb + (size_t)b0row * N + b0nc * 4);
        cp16(&Bs0[b1row * BPITCH + b1nc * 4], Bb + (size_t)b1row * N + b1nc * 4);
        asm volatile("cp.async.commit_group;\n");
    }

    int buf = 0;
    for (int kt = 0; kt < nk; kt++) {
        asm volatile("cp.async.wait_group 0;\n");
        __syncthreads();

        if (kt + 1 < nk) {
            int kb = (kt + 1) * 16;
            float* An = AsA[buf ^ 1];
            float* Bn = BsA[buf ^ 1];
#pragma unroll
            for (int j = 0; j < 4; j++)
                cp16(&An[arow[j] * APITCH + akc * 4], Ab + (size_t)arow[j] * K + kb + akc * 4);
            cp16(&Bn[b0row * BPITCH + b0nc * 4], Bb + (size_t)(kb + b0row) * N + b0nc * 4);
            cp16(&Bn[b1row * BPITCH + b1nc * 4], Bb + (size_t)(kb + b1row) * N + b1nc * 4);
        }
        asm volatile("cp.async.commit_group;\n");

        const float* Asb = AsA[buf];
        const float* Bsb = BsA[buf];
        int r  = lane >> 2;
        int kc = lane & 3;
#pragma unroll
        for (int ks = 0; ks < 2; ks++) {
            int k0 = ks * 8;
            unsigned af[4][4];
#pragma unroll
            for (int mf = 0; mf < 4; mf++) {
                int m = wm + mf * 16;
                af[mf][0] = __float_as_uint(Asb[(m + r)     * APITCH + k0 + kc]);
                af[mf][1] = __float_as_uint(Asb[(m + r + 8) * APITCH + k0 + kc]);
                af[mf][2] = __float_as_uint(Asb[(m + r)     * APITCH + k0 + kc + 4]);
                af[mf][3] = __float_as_uint(Asb[(m + r + 8) * APITCH + k0 + kc + 4]);
            }
            unsigned bfr[8][2];
#pragma unroll
            for (int nf = 0; nf < 8; nf++) {
                int n = wn + nf * 8;
                bfr[nf][0] = __float_as_uint(Bsb[(k0 + kc)     * BPITCH + n + r]);
                bfr[nf][1] = __float_as_uint(Bsb[(k0 + kc + 4) * BPITCH + n + r]);
            }
#pragma unroll
            for (int mf = 0; mf < 4; mf++)
#pragma unroll
                for (int nf = 0; nf < 8; nf++)
                    mma_tf32(acc[mf][nf], af[mf][0], af[mf][1], af[mf][2], af[mf][3],
                             bfr[nf][0], bfr[nf][1]);
        }
        buf ^= 1;
    }

    int r  = lane >> 2;
    int cc = (lane & 3) * 2;
#pragma unroll
    for (int mf = 0; mf < 4; mf++) {
#pragma unroll
        for (int nf = 0; nf < 8; nf++) {
            size_t row0 = (size_t)(by * 256 + wm + mf * 16 + r);
            int col = bx * 128 + wn + nf * 8 + cc;
            *(float2*)&C[row0 * N + col]       = make_float2(acc[mf][nf][0], acc[mf][nf][1]);
            *(float2*)&C[(row0 + 8) * N + col] = make_float2(acc[mf][nf][2], acc[mf][nf][3]);
        }
    }
}

// ---------------- Q: RMSNorm + RoPE + scale -> tf32 bits ----------------
__global__ void qnorm_rope(const float* __restrict__ qg, float* __restrict__ qout,
                           const float* __restrict__ w, const float* __restrict__ cs,
                           const float* __restrict__ sn) {
    int t = blockIdx.x;
    int bh = blockIdx.y;
    int b = bh >> 4, h = bh & 15;
    int i = threadIdx.x;  // 128

    const float* row = qg + (((size_t)(b * T_ + t) * H_ + h) * 2 * HD_);
    float v = row[i];

    float ss = v * v;
#pragma unroll
    for (int o = 16; o > 0; o >>= 1) ss += __shfl_xor_sync(0xffffffffu, ss, o);
    __shared__ float warpsum[4];
    __shared__ float normed[HD_];
    if ((i & 31) == 0) warpsum[i >> 5] = ss;
    __syncthreads();
    float tot = warpsum[0] + warpsum[1] + warpsum[2] + warpsum[3];
    float rms = rsqrtf(tot * (1.0f / HD_) + 1e-6f);
    float xv = v * rms * w[i];
    normed[i] = xv;
    __syncthreads();
    float rot = (i < 64) ? -normed[i + 64] : normed[i - 64];
    float o = (xv * cs[t * HD_ + i] + rot * sn[t * HD_ + i]) * 0.08838834764831845f;
    ((unsigned*)qout)[(((size_t)(b * H_ + h) * T_) + t) * HD_ + i] = f2tf32(o);
}

// ---------------- K: RMSNorm + RoPE -> tf32 bits (in place) ----------------
__global__ void knorm_rope(float* __restrict__ kbuf, const float* __restrict__ w,
                           const float* __restrict__ cs, const float* __restrict__ sn) {
    int t = blockIdx.x;
    int bg = blockIdx.y;
    int b = bg >> 2, g = bg & 3;
    int i = threadIdx.x;

    size_t base = ((size_t)(b * T_ + t) * G_ + g) * HD_;
    float v = kbuf[base + i];

    float ss = v * v;
#pragma unroll
    for (int o = 16; o > 0; o >>= 1) ss += __shfl_xor_sync(0xffffffffu, ss, o);
    __shared__ float warpsum[4];
    __shared__ float normed[HD_];
    if ((i & 31) == 0) warpsum[i >> 5] = ss;
    __syncthreads();
    float tot = warpsum[0] + warpsum[1] + warpsum[2] + warpsum[3];
    float rms = rsqrtf(tot * (1.0f / HD_) + 1e-6f);
    float xv = v * rms * w[i];
    normed[i] = xv;
    __syncthreads();
    float rot = (i < 64) ? -normed[i + 64] : normed[i - 64];
    ((unsigned*)kbuf)[base + i] = f2tf32(xv * cs[t * HD_ + i] + rot * sn[t * HD_ + i]);
}

// ---------------- causal GQA flash attention on tf32 tensor cores ----------------
#define QP 132
#define VP 136
#define SP 68
#define FLASH_SMEM ((64 * QP * 2 + 64 * VP + 64 * SP * 2 + 3 * 64) * 4)

__global__ __launch_bounds__(256, 1) void flash_tc(
        const float* __restrict__ Q, const float* __restrict__ K,
        const float* __restrict__ V, const float* __restrict__ qg,
        float* __restrict__ Oout) {
    extern __shared__ float sm[];
    float* Qs   = sm;
    float* Ks   = Qs + 64 * QP;
    float* Vs   = Ks + 64 * QP;
    float* Sh   = Vs + 64 * VP;
    float* Sl   = Sh + 64 * SP;
    float* rowm = Sl + 64 * SP;
    float* rowl = rowm + 64;
    float* ralp = rowl + 64;

    int qt = gridDim.x - 1 - blockIdx.x;
    int bh = blockIdx.y;
    int b = bh >> 4, h = bh & 15;
    int g = h >> 2;
    int tid = threadIdx.x;
    int w = tid >> 5, lane = tid & 31;
    int m0  = (w & 3) * 16;
    int n0s = (w >> 2) * 32;
    int n0d = (w >> 2) * 64;
    int lr = lane >> 2, lc = lane & 3;

    const float* Qb = Q + (((size_t)(b * H_ + h) * T_) + qt * 64) * HD_;
    const float* Kb = K + ((size_t)b * T_ * G_ + g) * HD_;
    const float* Vb = V + ((size_t)b * T_ * G_ + g) * HD_;

    for (int i = tid; i < 64 * 32; i += 256) {
        int r = i >> 5, c4 = (i & 31) * 4;
        *(float4*)&Qs[r * QP + c4] = *(const float4*)(Qb + r * HD_ + c4);
    }
    if (tid < 64) { rowm[tid] = -3e30f; rowl[tid] = 0.f; }

    float o[8][4];
#pragma unroll
    for (int nf = 0; nf < 8; nf++)
#pragma unroll
        for (int c = 0; c < 4; c++) o[nf][c] = 0.f;
    __syncthreads();

    for (int j = 0; j <= qt; j++) {
        const float* Kt = Kb + (size_t)(j * 64) * (G_ * HD_);
        const float* Vt = Vb + (size_t)(j * 64) * (G_ * HD_);
        for (int i = tid; i < 64 * 32; i += 256) {
            int r = i >> 5, c4 = (i & 31) * 4;
            *(float4*)&Ks[r * QP + c4] = *(const float4*)(Kt + (size_t)r * (G_ * HD_) + c4);
            *(float4*)&Vs[r * VP + c4] = *(const float4*)(Vt + (size_t)r * (G_ * HD_) + c4);
        }
        __syncthreads();

        float s[4][4];
#pragma unroll
        for (int nf = 0; nf < 4; nf++)
#pragma unroll
            for (int c = 0; c < 4; c++) s[nf][c] = 0.f;

#pragma unroll
        for (int ks = 0; ks < 16; ks++) {
            int k0 = ks * 8;
            unsigned a0 = __float_as_uint(Qs[(m0 + lr)     * QP + k0 + lc]);
            unsigned a1 = __float_as_uint(Qs[(m0 + lr + 8) * QP + k0 + lc]);
            unsigned a2 = __float_as_uint(Qs[(m0 + lr)     * QP + k0 + lc + 4]);
            unsigned a3 = __float_as_uint(Qs[(m0 + lr + 8) * QP + k0 + lc + 4]);
#pragma unroll
            for (int nf = 0; nf < 4; nf++) {
                int n = n0s + nf * 8;
                unsigned b0 = __float_as_uint(Ks[(n + lr) * QP + k0 + lc]);
                unsigned b1 = __float_as_uint(Ks[(n + lr) * QP + k0 + lc + 4]);
                mma_tf32(s[nf], a0, a1, a2, a3, b0, b1);
            }
        }

#pragma unroll
        for (int nf = 0; nf < 4; nf++) {
            int col = n0s + nf * 8 + lc * 2;
            *(float2*)&Sh[(m0 + lr)     * SP + col] = make_float2(s[nf][0], s[nf][1]);
            *(float2*)&Sh[(m0 + lr + 8) * SP + col] = make_float2(s[nf][2], s[nf][3]);
        }
        __syncthreads();

        if (tid < 64) {
            int rr = tid;
            float* Sr = &Sh[rr * SP];
            float* Lr = &Sl[rr * SP];
            bool diag = (j == qt);
            float m = rowm[rr], mn = m;
#pragma unroll 8
            for (int c = 0; c < 64; c++) {
                float sv = (diag && c > rr) ? -3e30f : Sr[c];
                mn = fmaxf(mn, sv);
            }
            float a = __expf(m - mn);
            float l = rowl[rr] * a;
#pragma unroll 8
            for (int c = 0; c < 64; c++) {
                float sv = (diag && c > rr) ? -3e30f : Sr[c];
                float p = __expf(sv - mn);
                l += p;
                unsigned ph = f2tf32(p);
                float pl = p - __uint_as_float(ph);
                Sr[c] = __uint_as_float(ph);
                Lr[c] = __uint_as_float(f2tf32(pl));
            }
            rowm[rr] = mn; rowl[rr] = l; ralp[rr] = a;
        }
        __syncthreads();

        float aL = ralp[m0 + lr], aH = ralp[m0 + 8 + lr];
#pragma unroll
        for (int nf = 0; nf < 8; nf++) {
            o[nf][0] *= aL; o[nf][1] *= aL; o[nf][2] *= aH; o[nf][3] *= aH;
        }

#pragma unroll
        for (int ks = 0; ks < 8; ks++) {
            int k0 = ks * 8;
            unsigned h0 = __float_as_uint(Sh[(m0 + lr)     * SP + k0 + lc]);
            unsigned h1 = __float_as_uint(Sh[(m0 + lr + 8) * SP + k0 + lc]);
            unsigned h2 = __float_as_uint(Sh[(m0 + lr)     * SP + k0 + lc + 4]);
            unsigned h3 = __float_as_uint(Sh[(m0 + lr + 8) * SP + k0 + lc + 4]);
            unsigned l0 = __float_as_uint(Sl[(m0 + lr)     * SP + k0 + lc]);
            unsigned l1 = __float_as_uint(Sl[(m0 + lr + 8) * SP + k0 + lc]);
            unsigned l2 = __float_as_uint(Sl[(m0 + lr)     * SP + k0 + lc + 4]);
            unsigned l3 = __float_as_uint(Sl[(m0 + lr + 8) * SP + k0 + lc + 4]);
#pragma unroll
            for (int nf = 0; nf < 8; nf++) {
                int n = n0d + nf * 8;
                unsigned b0 = __float_as_uint(Vs[(k0 + lc)     * VP + n + lr]);
                unsigned b1 = __float_as_uint(Vs[(k0 + lc + 4) * VP + n + lr]);
                mma_tf32(o[nf], h0, h1, h2, h3, b0, b1);
                mma_tf32(o[nf], l0, l1, l2, l3, b0, b1);
            }
        }
        __syncthreads();
    }

#pragma unroll
    for (int half = 0; half < 2; half++) {
        int rr = m0 + half * 8 + lr;
        float linv = 1.0f / rowl[rr];
        int grow = qt * 64 + rr;
        const float* gbase = qg + (((size_t)(b * T_ + grow) * H_ + h) * 2 * HD_) + HD_;
        unsigned* obase = (unsigned*)(Oout + ((size_t)(b * T_ + grow) * (H_ * HD_)) + h * HD_);
#pragma unroll
        for (int nf = 0; nf < 8; nf++) {
            int d = n0d + nf * 8 + lc * 2;
#pragma unroll
            for (int e = 0; e < 2; e++) {
                float gt = gbase[d + e];
                float sg = 1.0f / (1.0f + __expf(-gt));
                float val = o[nf][half * 2 + e] * linv * sg;
                obase[d + e] = f2tf32(val);
            }
        }
    }
}

// ---------------- launch ----------------
extern "C" void kernel_launch(void* const* d_in, const int* in_sizes, int n_in,
                              void* d_out, int out_size) {
    const float* x    = (const float*)d_in[0];
    const float* w_q  = (const float*)d_in[1];
    const float* w_k  = (const float*)d_in[2];
    const float* w_v  = (const float*)d_in[3];
    const float* w_o  = (const float*)d_in[4];
    const float* qnw  = (const float*)d_in[5];
    const float* knw  = (const float*)d_in[6];
    const float* cs   = (const float*)d_in[7];
    const float* sn   = (const float*)d_in[8];
    float* out = (float*)d_out;

    float *qg, *q, *k, *v, *attn, *xt, *wqt, *wkt, *wvt, *wot;
    cudaGetSymbolAddress((void**)&qg,   g_qg);
    cudaGetSymbolAddress((void**)&q,    g_q);
    cudaGetSymbolAddress((void**)&k,    g_k);
    cudaGetSymbolAddress((void**)&v,    g_v);
    cudaGetSymbolAddress((void**)&attn, g_attn);
    cudaGetSymbolAddress((void**)&xt,   g_xt);
    cudaGetSymbolAddress((void**)&wqt,  g_wqt);
    cudaGetSymbolAddress((void**)&wkt,  g_wkt);
    cudaGetSymbolAddress((void**)&wvt,  g_wvt);
    cudaGetSymbolAddress((void**)&wot,  g_wot);

    cudaFuncSetAttribute((const void*)flash_tc,
                         cudaFuncAttributeMaxDynamicSharedMemorySize, FLASH_SMEM);
    cudaFuncSetAttribute((const void*)gemm_tf32_256,
                         cudaFuncAttributeMaxDynamicSharedMemorySize, G2_SMEM);

    const int M = B_ * T_;  // 4096

    // tf32 rounding pre-pass
    {
        int n4;
        n4 = (B_ * T_ * D_) / 4;          cvt_tf32<<<(n4 + 255) / 256, 256>>>(x,   xt,  n4);
        n4 = (D_ * 2 * H_ * HD_) / 4;     cvt_tf32<<<(n4 + 255) / 256, 256>>>(w_q, wqt, n4);
        n4 = (D_ * G_ * HD_) / 4;         cvt_tf32<<<(n4 + 255) / 256, 256>>>(w_k, wkt, n4);
        n4 = (D_ * G_ * HD_) / 4;         cvt_tf32<<<(n4 + 255) / 256, 256>>>(w_v, wvt, n4);
        n4 = (H_ * HD_ * D_) / 4;         cvt_tf32<<<(n4 + 255) / 256, 256>>>(w_o, wot, n4);
    }

    // QKV projections (tensor cores, tf32)
    gemm_tf32_256<<<dim3((2 * H_ * HD_) / 128, M / 256), 256, G2_SMEM>>>(xt, wqt, qg, M, 2 * H_ * HD_, D_);
    gemm_tf32<<<dim3((G_ * HD_) / 128, M / 128), 256>>>(xt, wkt, k, M, G_ * HD_, D_);
    gemm_tf32<<<dim3((G_ * HD_) / 128, M / 128), 256>>>(xt, wvt, v, M, G_ * HD_, D_);

    // norms + rope (emit tf32 bits); V -> tf32 bits
    qnorm_rope<<<dim3(T_, B_ * H_), 128>>>(qg, q, qnw, cs, sn);
    knorm_rope<<<dim3(T_, B_ * G_), 128>>>(k, knw, cs, sn);
    {
        int n4 = (B_ * T_ * G_ * HD_) / 4;
        cvt_tf32<<<(n4 + 255) / 256, 256>>>(v, v, n4);
    }

    // attention + gate (tf32 tensor cores)
    flash_tc<<<dim3(T_ / 64, B_ * H_), 256, FLASH_SMEM>>>(q, k, v, qg, attn);

    // output projection (tensor cores, tf32)
    gemm_tf32_256<<<dim3(D_ / 128, M / 256), 256, G2_SMEM>>>(attn, wot, out, M, D_, D_);
}